// round 13
// baseline (speedup 1.0000x reference)
#include <cuda_runtime.h>
#include <math.h>

#define WPB    8
#define BLOCK  (WPB * 32)        // 256 == NCELLS
#define HBUF   128
#define GRIDC  16
#define NCELLS (GRIDC * GRIDC)
#define NMAXSM 2048              // max nodes binned in smem
#define KPT    (NMAXSM / BLOCK)  // 8 nodes per thread

__device__ __forceinline__ int clampi(int v, int lo, int hi) {
    return v < lo ? lo : (v > hi ? hi : v);
}

__device__ __forceinline__ int cell_of(float x, float y) {
    int cx = clampi((int)(x * (float)GRIDC), 0, GRIDC - 1);
    int cy = clampi((int)(y * (float)GRIDC), 0, GRIDC - 1);
    return cy * GRIDC + cx;
}

// Dense-hat KAN with vectorized weight loads.
__device__ __forceinline__ float kan_softplus(float u, float v,
                                              const float2* __restrict__ s_w1,
                                              const float* __restrict__ s_w2p) {
    const float inv_h = 1.0f / 0.75f;
    float b0[5], b1[5];
    #pragma unroll
    for (int k = 0; k < 5; k++) {
        float g = -1.5f + 0.75f * (float)k;
        b0[k] = fmaxf(0.0f, fmaf(-fabsf(u - g), inv_h, 1.0f));
        b1[k] = fmaxf(0.0f, fmaf(-fabsf(v - g), inv_h, 1.0f));
    }
    float acc0 = 0.0f, acc1 = 0.0f;
    #pragma unroll
    for (int j = 0; j < 8; j++) {
        float hd = 0.0f;
        #pragma unroll
        for (int k = 0; k < 5; k++) {
            float2 wv = s_w1[j * 5 + k];
            hd = fmaf(b0[k], wv.x, fmaf(b1[k], wv.y, hd));
        }
        float4 w4 = *reinterpret_cast<const float4*>(&s_w2p[j * 8]);
        float  w4e = s_w2p[j * 8 + 4];
        float wk[5] = {w4.x, w4.y, w4.z, w4.w, w4e};
        float a = 0.0f;
        #pragma unroll
        for (int k = 0; k < 5; k++) {
            float g = -1.5f + 0.75f * (float)k;
            a += fmaxf(0.0f, fmaf(-fabsf(hd - g), inv_h, 1.0f)) * wk[k];
        }
        if (j & 1) acc1 += a; else acc0 += a;
    }
    float acc = acc0 + acc1;
    return (acc > 20.0f) ? acc : __logf(1.0f + __expf(acc));
}

__device__ __forceinline__ float cubic_window(float q) {
    if (q <= 0.5f)
        return 2.0f / 3.0f + q * q * (4.0f * q - 4.0f);
    return 4.0f / 3.0f + q * (-4.0f + q * (4.0f - (4.0f / 3.0f) * q));
}

// Cold path: dense in-radius accumulation straight from global arrays.
__device__ __noinline__ void dense_accum(float px, float py,
                                         const float2* __restrict__ nd2,
                                         const float* __restrict__ w, int N, int lane,
                                         float& lsum, float& lws,
                                         const float2* __restrict__ s_w1,
                                         const float* __restrict__ s_w2p)
{
    const float inv_r = 1.0f / 0.06f;
    const float r2 = 0.06f * 0.06f;
    lsum = 0.0f; lws = 0.0f;
    for (int n = lane; n < N; n += 32) {
        float2 nd = __ldg(&nd2[n]);
        float dx = px - nd.x;
        float dy = py - nd.y;
        float d2 = fmaf(dx, dx, dy * dy);
        if (d2 <= r2) {
            float sp = kan_softplus(dx * inv_r, dy * inv_r, s_w1, s_w2p);
            float phi = sp * cubic_window(sqrtf(d2) * inv_r);
            lsum += phi;
            lws  += phi * __ldg(&w[n]);
        }
    }
}

// Cold path: exact warp-local kNN (k=8) fallback; writes out[m].
__device__ __noinline__ void orphan_knn(float px, float py,
                                        const float2* __restrict__ nd2,
                                        const float* __restrict__ w, int N, int lane,
                                        float* __restrict__ out, int m)
{
    const int kk = (N < 8) ? N : 8;
    unsigned long long last = 0ull;
    float seld = 0.0f;
    int   seli = 0;
    for (int r = 0; r < kk; r++) {
        unsigned long long best = 0xffffffffffffffffull;
        for (int n = lane; n < N; n += 32) {
            float2 nd = __ldg(&nd2[n]);
            float dx = px - nd.x;
            float dy = py - nd.y;
            float dist = sqrtf(fmaf(dx, dx, dy * dy));
            unsigned long long key =
                (((unsigned long long)__float_as_uint(dist)) << 32) |
                (unsigned long long)(unsigned)n;
            if ((r == 0 || key > last) && key < best) best = key;
        }
        #pragma unroll
        for (int off = 16; off > 0; off >>= 1) {
            unsigned long long o = __shfl_xor_sync(0xffffffffu, best, off);
            best = (o < best) ? o : best;
        }
        last = best;
        if (lane == r) {
            seld = __uint_as_float((unsigned)(best >> 32));
            seli = (int)(best & 0xffffffffull);
        }
    }
    float e = 0.0f, ew = 0.0f;
    if (lane < kk) {
        e  = expf(-(20.0f / 0.06f) * seld);
        ew = e * __ldg(&w[seli]);
    }
    #pragma unroll
    for (int off = 16; off > 0; off >>= 1) {
        e  += __shfl_xor_sync(0xffffffffu, e,  off);
        ew += __shfl_xor_sync(0xffffffffu, ew, off);
    }
    if (lane == 0) out[m] = ew / (e + 1e-18f);
}

__global__ __launch_bounds__(BLOCK, 2) void mkan_kernel(
    const float* __restrict__ x, const float* __restrict__ nodes,
    const float* __restrict__ w, const float* __restrict__ w1a,
    const float* __restrict__ w1b, const float* __restrict__ w2,
    float* __restrict__ out, int M, int N, int use_bins)
{
    __shared__ float2 s_w1[40];                      // (w1a, w1b) pairs
    __shared__ __align__(16) float s_w2p[64];        // w2 rows padded to 8
    __shared__ __align__(16) float4 s_cs[NMAXSM];    // block-private binned nodes
    __shared__ int    s_cstart[NCELLS + 1];
    __shared__ int    s_hist[NCELLS];                // histogram / scatter cursors
    __shared__ int    s_wsum[WPB];
    __shared__ int    s_hits[WPB][HBUF];             // compacted smem indices

    const int tid  = threadIdx.x;
    const int wid  = tid >> 5;
    const int lane = tid & 31;

    const int m = blockIdx.x * WPB + wid;
    const int mc = (m < M) ? m : (M - 1);

    // Prefetch x early; latency hides under binning.
    const float2 p = __ldg(&((const float2*)x)[mc]);

    // Stage weights.
    if (tid < 40)
        s_w1[tid] = make_float2(__ldg(&w1a[tid]), __ldg(&w1b[tid]));
    else if (tid >= 64 && tid < 128) {
        int i = tid - 64;
        int row = i >> 3, col = i & 7;
        s_w2p[i] = (col < 5) ? __ldg(&w2[row * 5 + col]) : 0.0f;
    }
    s_hist[tid] = 0;                                 // BLOCK == NCELLS

    const float2* __restrict__ nd2 = (const float2*)nodes;
    const bool binned = (use_bins != 0);

    float nx[KPT], ny[KPT], wv[KPT];
    int   cc[KPT];

    if (binned) {
        __syncthreads();   // s_hist zeroed before atomics

        // ---- Bin pass 1: load nodes+w into registers, histogram ----
        #pragma unroll
        for (int k = 0; k < KPT; k++) {
            const int n = k * BLOCK + tid;
            cc[k] = -1;
            if (n < N) {
                float2 nd = __ldg(&nd2[n]);
                nx[k] = nd.x; ny[k] = nd.y;
                wv[k] = __ldg(&w[n]);
                cc[k] = cell_of(nd.x, nd.y);
                atomicAdd(&s_hist[cc[k]], 1);
            }
        }
        __syncthreads();

        // ---- Exclusive scan of 256 cell counts (warp scans + offsets) ----
        int v0 = s_hist[tid];
        int incl = v0;
        #pragma unroll
        for (int o = 1; o < 32; o <<= 1) {
            int t = __shfl_up_sync(0xffffffffu, incl, o);
            if (lane >= o) incl += t;
        }
        if (lane == 31) s_wsum[wid] = incl;
        __syncthreads();
        if (tid == 0) {
            int acc = 0;
            #pragma unroll
            for (int i = 0; i < WPB; i++) { int t = s_wsum[i]; s_wsum[i] = acc; acc += t; }
        }
        __syncthreads();
        {
            int excl = incl - v0 + s_wsum[wid];
            s_cstart[tid] = excl;
            s_hist[tid] = excl;                      // reuse as scatter cursor
            if (tid == 0) s_cstart[NCELLS] = N;
        }
        __syncthreads();

        // ---- Bin pass 2: scatter from registers into smem CSR ----
        #pragma unroll
        for (int k = 0; k < KPT; k++) {
            if (cc[k] >= 0) {
                int pos = atomicAdd(&s_hist[cc[k]], 1);
                s_cs[pos] = make_float4(nx[k], ny[k], wv[k], 0.0f);
            }
        }
        __syncthreads();
    } else {
        __syncthreads();   // weights staged
    }

    if (m >= M) return;

    const float px = p.x, py = p.y;
    const float radius = 0.06f;
    const float inv_r  = 1.0f / 0.06f;
    const float r2     = radius * radius;

    float lsum = 0.0f, lws = 0.0f;
    bool dense = !binned;

    if (!dense) {
        const int cx0 = clampi((int)floorf((px - radius) * (float)GRIDC), 0, GRIDC - 1);
        const int cx1 = clampi((int)floorf((px + radius) * (float)GRIDC), 0, GRIDC - 1);
        const int cy0 = clampi((int)floorf((py - radius) * (float)GRIDC), 0, GRIDC - 1);
        const int cy1 = clampi((int)floorf((py + radius) * (float)GRIDC), 0, GRIDC - 1);
        const int nrows = cy1 - cy0 + 1;   // <= 3

        int rs[3], re[3];
        #pragma unroll
        for (int r = 0; r < 3; r++) {
            if (r < nrows) {
                rs[r] = s_cstart[(cy0 + r) * GRIDC + cx0];
                re[r] = s_cstart[(cy0 + r) * GRIDC + cx1 + 1];
            } else {
                rs[r] = 0; re[r] = 0;
            }
        }

        int hits = 0;
        const bool fast = (re[0] - rs[0] <= 32) & (re[1] - rs[1] <= 32) & (re[2] - rs[2] <= 32);
        if (fast) {
            // ---- Phase A (fast): 3 parallel LDS.128 rounds, 3 ballots ----
            bool hit[3];
            int  iv[3];
            #pragma unroll
            for (int r = 0; r < 3; r++) {
                const int i = rs[r] + lane;
                iv[r] = i;
                hit[r] = false;
                if (i < re[r]) {
                    float4 nd = s_cs[i];
                    float dx = px - nd.x;
                    float dy = py - nd.y;
                    hit[r] = (fmaf(dx, dx, dy * dy) <= r2);
                }
            }
            const unsigned lt = (1u << lane) - 1u;
            #pragma unroll
            for (int r = 0; r < 3; r++) {
                unsigned msk = __ballot_sync(0xffffffffu, hit[r]);
                if (hit[r]) {
                    int pos = hits + __popc(msk & lt);  // max 95 < HBUF
                    s_hits[wid][pos] = iv[r];
                }
                hits += __popc(msk);
            }
        } else {
            // ---- Phase A (serial fallback): chunked ballot-compaction ----
            #pragma unroll
            for (int r = 0; r < 3; r++) {
                for (int base = rs[r]; base < re[r]; base += 32) {
                    const int i = base + lane;
                    bool hit = false;
                    if (i < re[r]) {
                        float4 nd = s_cs[i];
                        float dx = px - nd.x;
                        float dy = py - nd.y;
                        hit = (fmaf(dx, dx, dy * dy) <= r2);
                    }
                    unsigned msk = __ballot_sync(0xffffffffu, hit);
                    if (hit) {
                        int pos = hits + __popc(msk & ((1u << lane) - 1u));
                        if (pos < HBUF) s_hits[wid][pos] = i;
                    }
                    hits += __popc(msk);
                }
            }
        }
        __syncwarp();

        if (hits <= 32) {
            // ---- Phase B (common): single-shot, straight-line KAN ----
            if (lane < hits) {
                float4 nd = s_cs[s_hits[wid][lane]];
                float dx = px - nd.x;
                float dy = py - nd.y;
                float d2 = fmaf(dx, dx, dy * dy);
                float sp = kan_softplus(dx * inv_r, dy * inv_r, s_w1, s_w2p);
                float phi = sp * cubic_window(sqrtf(d2) * inv_r);
                lsum = phi;
                lws  = phi * nd.z;
            }
        } else if (hits <= HBUF) {
            for (int i = lane; i < hits; i += 32) {
                float4 nd = s_cs[s_hits[wid][i]];
                float dx = px - nd.x;
                float dy = py - nd.y;
                float d2 = fmaf(dx, dx, dy * dy);
                float sp = kan_softplus(dx * inv_r, dy * inv_r, s_w1, s_w2p);
                float phi = sp * cubic_window(sqrtf(d2) * inv_r);
                lsum += phi;
                lws  += phi * nd.z;
            }
        } else {
            dense = true;
        }
    }

    if (dense)
        dense_accum(px, py, nd2, w, N, lane, lsum, lws, s_w1, s_w2p);

    // ---- Warp butterfly reduction ----
    #pragma unroll
    for (int off = 16; off > 0; off >>= 1) {
        lsum += __shfl_xor_sync(0xffffffffu, lsum, off);
        lws  += __shfl_xor_sync(0xffffffffu, lws,  off);
    }

    if (lsum >= 1e-14f) {
        if (lane == 0) out[m] = lws / (lsum + 1e-12f);
        return;
    }

    orphan_knn(px, py, nd2, w, N, lane, out, m);
}

extern "C" void kernel_launch(void* const* d_in, const int* in_sizes, int n_in,
                              void* d_out, int out_size) {
    const float* x     = (const float*)d_in[0];
    const float* nodes = (const float*)d_in[1];
    const float* w     = (const float*)d_in[2];
    const float* w1a   = (const float*)d_in[3];
    const float* w1b   = (const float*)d_in[4];
    const float* w2    = (const float*)d_in[5];
    float* out = (float*)d_out;

    int M = in_sizes[0] / 2;
    int N = in_sizes[1] / 2;

    int use_bins = (N <= NMAXSM) ? 1 : 0;
    int grid = (M + WPB - 1) / WPB;
    mkan_kernel<<<grid, BLOCK>>>(x, nodes, w, w1a, w1b, w2, out, M, N, use_bins);
}

// round 14
// speedup vs baseline: 1.5446x; 1.5446x over previous
#include <cuda_runtime.h>
#include <math.h>

#define WPB    8
#define BLOCK  (WPB * 32)
#define HBUF   128
#define GRIDC  16
#define NCELLS (GRIDC * GRIDC)
#define MAXN   4096
#define BINT   1024

// CSR-binned nodes: d_cs[i] = (x, y, w, unused), cells contiguous, row-major cells.
__device__ float4 d_cs[MAXN];
__device__ int    d_cstart[NCELLS + 1];

__device__ __forceinline__ int clampi(int v, int lo, int hi) {
    return v < lo ? lo : (v > hi ? hi : v);
}

__device__ __forceinline__ int cell_of(float x, float y) {
    int cx = clampi((int)(x * (float)GRIDC), 0, GRIDC - 1);
    int cy = clampi((int)(y * (float)GRIDC), 0, GRIDC - 1);
    return cy * GRIDC + cx;
}

// Single-block CSR counting sort. Fast path: N even, N<=2*BINT -> each thread
// owns 2 nodes in registers (single pass over memory). Generic fallback otherwise.
__global__ __launch_bounds__(BINT) void bin_kernel(const float* __restrict__ nodes,
                                                   const float* __restrict__ w, int N)
{
    __shared__ int h[NCELLS];
    __shared__ int off[NCELLS];
    __shared__ int wsum[8];
    const int tid = threadIdx.x;
    const float2* __restrict__ nd2 = (const float2*)nodes;

    if (tid < NCELLS) h[tid] = 0;
    __syncthreads();

    const bool fastN = ((N & 1) == 0) && (N <= 2 * BINT);

    float2 a = make_float2(0.f, 0.f), b = make_float2(0.f, 0.f);
    float2 wv = make_float2(0.f, 0.f);
    int c0 = -1, c1 = -1;
    bool own = false;

    if (fastN) {
        const int n0 = tid * 2;
        if (n0 < N) {
            own = true;
            float4 nd = __ldg(&((const float4*)nodes)[tid]);   // two float2 nodes
            a = make_float2(nd.x, nd.y);
            b = make_float2(nd.z, nd.w);
            wv = __ldg(&((const float2*)w)[tid]);
            c0 = cell_of(a.x, a.y);
            c1 = cell_of(b.x, b.y);
            atomicAdd(&h[c0], 1);
            atomicAdd(&h[c1], 1);
        }
    } else {
        for (int n = tid; n < N; n += BINT) {
            float2 nd = __ldg(&nd2[n]);
            atomicAdd(&h[cell_of(nd.x, nd.y)], 1);
        }
    }
    __syncthreads();

    // Exclusive scan of 256 counts.
    int v0 = 0, incl = 0;
    if (tid < NCELLS) {
        v0 = h[tid];
        incl = v0;
        const int lane = tid & 31;
        #pragma unroll
        for (int o = 1; o < 32; o <<= 1) {
            int t = __shfl_up_sync(0xffffffffu, incl, o);
            if (lane >= o) incl += t;
        }
        if (lane == 31) wsum[tid >> 5] = incl;
    }
    __syncthreads();
    if (tid == 0) {
        int acc = 0;
        #pragma unroll
        for (int i = 0; i < 8; i++) { int t = wsum[i]; wsum[i] = acc; acc += t; }
    }
    __syncthreads();
    if (tid < NCELLS) {
        int excl = incl - v0 + wsum[tid >> 5];
        d_cstart[tid] = excl;
        off[tid] = excl;
    }
    if (tid == 0) d_cstart[NCELLS] = N;
    __syncthreads();

    // Signal the dependent (main) kernel: it may launch and run its prologue
    // while we scatter. Its griddepcontrol.wait still orders all our writes.
    asm volatile("griddepcontrol.launch_dependents;");

    if (fastN) {
        if (own) {
            int p0 = atomicAdd(&off[c0], 1);
            d_cs[p0] = make_float4(a.x, a.y, wv.x, 0.0f);
            int p1 = atomicAdd(&off[c1], 1);
            d_cs[p1] = make_float4(b.x, b.y, wv.y, 0.0f);
        }
    } else {
        for (int n = tid; n < N; n += BINT) {
            float2 nd = __ldg(&nd2[n]);
            int c = cell_of(nd.x, nd.y);
            int pos = atomicAdd(&off[c], 1);
            d_cs[pos] = make_float4(nd.x, nd.y, __ldg(&w[n]), 0.0f);
        }
    }
}

// Dense-hat KAN. Hidden weights packed as 2x float4 + 1x float2 per hidden unit:
//   s_w1q[j*2+h] = (w1a[j][2h], w1b[j][2h], w1a[j][2h+1], w1b[j][2h+1])
//   s_w1e[j]     = (w1a[j][4],  w1b[j][4])
// Output weights padded to 8 per row (LDS.128 + LDS.32).
__device__ __forceinline__ float kan_softplus(float u, float v,
                                              const float4* __restrict__ s_w1q,
                                              const float2* __restrict__ s_w1e,
                                              const float* __restrict__ s_w2p) {
    const float inv_h = 1.0f / 0.75f;
    float b0[5], b1[5];
    #pragma unroll
    for (int k = 0; k < 5; k++) {
        float g = -1.5f + 0.75f * (float)k;
        b0[k] = fmaxf(0.0f, fmaf(-fabsf(u - g), inv_h, 1.0f));
        b1[k] = fmaxf(0.0f, fmaf(-fabsf(v - g), inv_h, 1.0f));
    }
    float acc0 = 0.0f, acc1 = 0.0f;
    #pragma unroll
    for (int j = 0; j < 8; j++) {
        float4 q0 = s_w1q[j * 2 + 0];
        float4 q1 = s_w1q[j * 2 + 1];
        float2 e  = s_w1e[j];
        // Same k-order FMA chain as the scalar version (k = 0..4).
        float hd = 0.0f;
        hd = fmaf(b0[0], q0.x, fmaf(b1[0], q0.y, hd));
        hd = fmaf(b0[1], q0.z, fmaf(b1[1], q0.w, hd));
        hd = fmaf(b0[2], q1.x, fmaf(b1[2], q1.y, hd));
        hd = fmaf(b0[3], q1.z, fmaf(b1[3], q1.w, hd));
        hd = fmaf(b0[4], e.x,  fmaf(b1[4], e.y,  hd));

        float4 w4 = *reinterpret_cast<const float4*>(&s_w2p[j * 8]);
        float  w4e = s_w2p[j * 8 + 4];
        float wk[5] = {w4.x, w4.y, w4.z, w4.w, w4e};
        float a = 0.0f;
        #pragma unroll
        for (int k = 0; k < 5; k++) {
            float g = -1.5f + 0.75f * (float)k;
            a += fmaxf(0.0f, fmaf(-fabsf(hd - g), inv_h, 1.0f)) * wk[k];
        }
        if (j & 1) acc1 += a; else acc0 += a;
    }
    float acc = acc0 + acc1;
    return (acc > 20.0f) ? acc : __logf(1.0f + __expf(acc));
}

__device__ __forceinline__ float cubic_window(float q) {
    if (q <= 0.5f)
        return 2.0f / 3.0f + q * q * (4.0f * q - 4.0f);
    return 4.0f / 3.0f + q * (-4.0f + q * (4.0f - (4.0f / 3.0f) * q));
}

// Cold path: dense in-radius accumulation straight from global arrays.
__device__ __noinline__ void dense_accum(float px, float py,
                                         const float2* __restrict__ nd2,
                                         const float* __restrict__ w, int N, int lane,
                                         float& lsum, float& lws,
                                         const float4* __restrict__ s_w1q,
                                         const float2* __restrict__ s_w1e,
                                         const float* __restrict__ s_w2p)
{
    const float inv_r = 1.0f / 0.06f;
    const float r2 = 0.06f * 0.06f;
    lsum = 0.0f; lws = 0.0f;
    for (int n = lane; n < N; n += 32) {
        float2 nd = __ldg(&nd2[n]);
        float dx = px - nd.x;
        float dy = py - nd.y;
        float d2 = fmaf(dx, dx, dy * dy);
        if (d2 <= r2) {
            float sp = kan_softplus(dx * inv_r, dy * inv_r, s_w1q, s_w1e, s_w2p);
            float phi = sp * cubic_window(sqrtf(d2) * inv_r);
            lsum += phi;
            lws  += phi * __ldg(&w[n]);
        }
    }
}

// Cold path: exact warp-local kNN (k=8) fallback; writes out[m].
__device__ __noinline__ void orphan_knn(float px, float py,
                                        const float2* __restrict__ nd2,
                                        const float* __restrict__ w, int N, int lane,
                                        float* __restrict__ out, int m)
{
    const int kk = (N < 8) ? N : 8;
    unsigned long long last = 0ull;
    float seld = 0.0f;
    int   seli = 0;
    for (int r = 0; r < kk; r++) {
        unsigned long long best = 0xffffffffffffffffull;
        for (int n = lane; n < N; n += 32) {
            float2 nd = __ldg(&nd2[n]);
            float dx = px - nd.x;
            float dy = py - nd.y;
            float dist = sqrtf(fmaf(dx, dx, dy * dy));
            unsigned long long key =
                (((unsigned long long)__float_as_uint(dist)) << 32) |
                (unsigned long long)(unsigned)n;
            if ((r == 0 || key > last) && key < best) best = key;
        }
        #pragma unroll
        for (int off = 16; off > 0; off >>= 1) {
            unsigned long long o = __shfl_xor_sync(0xffffffffu, best, off);
            best = (o < best) ? o : best;
        }
        last = best;
        if (lane == r) {
            seld = __uint_as_float((unsigned)(best >> 32));
            seli = (int)(best & 0xffffffffull);
        }
    }
    float e = 0.0f, ew = 0.0f;
    if (lane < kk) {
        e  = expf(-(20.0f / 0.06f) * seld);
        ew = e * __ldg(&w[seli]);
    }
    #pragma unroll
    for (int off = 16; off > 0; off >>= 1) {
        e  += __shfl_xor_sync(0xffffffffu, e,  off);
        ew += __shfl_xor_sync(0xffffffffu, ew, off);
    }
    if (lane == 0) out[m] = ew / (e + 1e-18f);
}

__global__ __launch_bounds__(BLOCK, 2) void mkan_kernel(
    const float* __restrict__ x, const float* __restrict__ nodes,
    const float* __restrict__ w, const float* __restrict__ w1a,
    const float* __restrict__ w1b, const float* __restrict__ w2,
    float* __restrict__ out, int M, int N, int use_bins)
{
    __shared__ __align__(16) float4 s_w1q[16];       // packed hidden weights
    __shared__ float2 s_w1e[8];                      // k=4 tails
    __shared__ __align__(16) float s_w2p[64];        // w2 rows padded to 8
    __shared__ float4 s_vals[WPB][HBUF];             // compacted (dx, dy, w, d2)

    const int tid  = threadIdx.x;
    const int wid  = tid >> 5;
    const int lane = tid & 31;

    const int m = blockIdx.x * WPB + wid;
    const int mc = (m < M) ? m : (M - 1);

    // ---- PDL prologue: everything here is independent of the bin kernel ----
    const float2 p = __ldg(&((const float2*)x)[mc]);

    if (tid < 16) {
        const int j = tid >> 1, k = (tid & 1) * 2;
        s_w1q[tid] = make_float4(__ldg(&w1a[j * 5 + k]),     __ldg(&w1b[j * 5 + k]),
                                 __ldg(&w1a[j * 5 + k + 1]), __ldg(&w1b[j * 5 + k + 1]));
    } else if (tid < 24) {
        const int j = tid - 16;
        s_w1e[j] = make_float2(__ldg(&w1a[j * 5 + 4]), __ldg(&w1b[j * 5 + 4]));
    } else if (tid >= 64 && tid < 128) {
        int i = tid - 64;
        int row = i >> 3, col = i & 7;
        s_w2p[i] = (col < 5) ? __ldg(&w2[row * 5 + col]) : 0.0f;
    }

    const float px = p.x, py = p.y;
    const float radius = 0.06f;
    const float inv_r  = 1.0f / 0.06f;
    const float r2     = radius * radius;
    const float2* __restrict__ nd2 = (const float2*)nodes;

    const int cx0 = clampi((int)floorf((px - radius) * (float)GRIDC), 0, GRIDC - 1);
    const int cx1 = clampi((int)floorf((px + radius) * (float)GRIDC), 0, GRIDC - 1);
    const int cy0 = clampi((int)floorf((py - radius) * (float)GRIDC), 0, GRIDC - 1);
    const int cy1 = clampi((int)floorf((py + radius) * (float)GRIDC), 0, GRIDC - 1);
    const int nrows = cy1 - cy0 + 1;   // <= 3

    __syncthreads();
    if (m >= M) return;

    // ---- Wait for bin kernel's writes (d_cstart / d_cs) to be visible ----
    asm volatile("griddepcontrol.wait;" ::: "memory");

    float lsum = 0.0f, lws = 0.0f;
    bool dense = (use_bins == 0);

    if (!dense) {
        // <=6 uniform direct loads of the range bounds (independent, one L2 trip).
        int rs[3], re[3];
        #pragma unroll
        for (int r = 0; r < 3; r++) {
            if (r < nrows) {
                rs[r] = __ldg(&d_cstart[(cy0 + r) * GRIDC + cx0]);
                re[r] = __ldg(&d_cstart[(cy0 + r) * GRIDC + cx1 + 1]);
            } else {
                rs[r] = 0; re[r] = 0;
            }
        }

        int hits = 0;
        const bool fast = (re[0] - rs[0] <= 32) & (re[1] - rs[1] <= 32) & (re[2] - rs[2] <= 32);
        if (fast) {
            // ---- Phase A (fast): one parallel memory round-trip for all 3 rows ----
            float dxv[3], dyv[3], wv[3], d2v[3];
            bool hit[3];
            #pragma unroll
            for (int r = 0; r < 3; r++) {
                const int i = rs[r] + lane;
                hit[r] = false;
                dxv[r] = dyv[r] = wv[r] = d2v[r] = 0.0f;
                if (i < re[r]) {
                    float4 nd = __ldg(&d_cs[i]);       // 3 independent LDG.128
                    dxv[r] = px - nd.x;
                    dyv[r] = py - nd.y;
                    wv[r]  = nd.z;
                    d2v[r] = fmaf(dxv[r], dxv[r], dyv[r] * dyv[r]);
                    hit[r] = (d2v[r] <= r2);
                }
            }
            const unsigned lt = (1u << lane) - 1u;
            #pragma unroll
            for (int r = 0; r < 3; r++) {
                unsigned msk = __ballot_sync(0xffffffffu, hit[r]);
                if (hit[r]) {
                    int pos = hits + __popc(msk & lt);  // max 95 < HBUF
                    s_vals[wid][pos] = make_float4(dxv[r], dyv[r], wv[r], d2v[r]);
                }
                hits += __popc(msk);
            }
        } else {
            // ---- Phase A (serial fallback): chunked ballot-compaction ----
            #pragma unroll
            for (int r = 0; r < 3; r++) {
                for (int base = rs[r]; base < re[r]; base += 32) {
                    const int i = base + lane;
                    bool hit = false;
                    float dx = 0.0f, dy = 0.0f, wvv = 0.0f, d2 = 0.0f;
                    if (i < re[r]) {
                        float4 nd = __ldg(&d_cs[i]);
                        dx = px - nd.x;
                        dy = py - nd.y;
                        wvv = nd.z;
                        d2 = fmaf(dx, dx, dy * dy);
                        hit = (d2 <= r2);
                    }
                    unsigned msk = __ballot_sync(0xffffffffu, hit);
                    if (hit) {
                        int pos = hits + __popc(msk & ((1u << lane) - 1u));
                        if (pos < HBUF) s_vals[wid][pos] = make_float4(dx, dy, wvv, d2);
                    }
                    hits += __popc(msk);
                }
            }
        }
        __syncwarp();

        if (hits <= 32) {
            // ---- Phase B (common): single-shot, straight-line KAN ----
            if (lane < hits) {
                float4 v = s_vals[wid][lane];
                float sp = kan_softplus(v.x * inv_r, v.y * inv_r, s_w1q, s_w1e, s_w2p);
                float phi = sp * cubic_window(sqrtf(v.w) * inv_r);
                lsum = phi;
                lws  = phi * v.z;
            }
        } else if (hits <= HBUF) {
            for (int i = lane; i < hits; i += 32) {
                float4 v = s_vals[wid][i];
                float sp = kan_softplus(v.x * inv_r, v.y * inv_r, s_w1q, s_w1e, s_w2p);
                float phi = sp * cubic_window(sqrtf(v.w) * inv_r);
                lsum += phi;
                lws  += phi * v.z;
            }
        } else {
            dense = true;
        }
    }

    if (dense)
        dense_accum(px, py, nd2, w, N, lane, lsum, lws, s_w1q, s_w1e, s_w2p);

    // ---- Warp butterfly reduction ----
    #pragma unroll
    for (int off = 16; off > 0; off >>= 1) {
        lsum += __shfl_xor_sync(0xffffffffu, lsum, off);
        lws  += __shfl_xor_sync(0xffffffffu, lws,  off);
    }

    if (lsum >= 1e-14f) {
        if (lane == 0) out[m] = lws / (lsum + 1e-12f);
        return;
    }

    orphan_knn(px, py, nd2, w, N, lane, out, m);
}

extern "C" void kernel_launch(void* const* d_in, const int* in_sizes, int n_in,
                              void* d_out, int out_size) {
    const float* x     = (const float*)d_in[0];
    const float* nodes = (const float*)d_in[1];
    const float* w     = (const float*)d_in[2];
    const float* w1a   = (const float*)d_in[3];
    const float* w1b   = (const float*)d_in[4];
    const float* w2    = (const float*)d_in[5];
    float* out = (float*)d_out;

    int M = in_sizes[0] / 2;
    int N = in_sizes[1] / 2;

    int use_bins = (N <= MAXN) ? 1 : 0;
    int grid = (M + WPB - 1) / WPB;

    if (use_bins) {
        bin_kernel<<<1, BINT>>>(nodes, w, N);

        // PDL: main kernel launches as soon as bin_kernel triggers
        // launch_dependents; its pre-wait prologue overlaps bin's scatter.
        cudaLaunchConfig_t cfg = {};
        cfg.gridDim = dim3((unsigned)grid, 1, 1);
        cfg.blockDim = dim3(BLOCK, 1, 1);
        cudaLaunchAttribute attr[1];
        attr[0].id = cudaLaunchAttributeProgrammaticStreamSerialization;
        attr[0].val.programmaticStreamSerializationAllowed = 1;
        cfg.attrs = attr;
        cfg.numAttrs = 1;
        cudaLaunchKernelEx(&cfg, mkan_kernel, x, nodes, w, w1a, w1b, w2,
                           out, M, N, use_bins);
    } else {
        mkan_kernel<<<grid, BLOCK>>>(x, nodes, w, w1a, w1b, w2, out, M, N, use_bins);
    }
}